// round 14
// baseline (speedup 1.0000x reference)
#include <cuda_runtime.h>
#include <cuda_fp16.h>

#define NN 200000
#define EE 3200000
#define HH 16
#define CC 4
#define GG 256
#define CAP 64   // bucket capacity per node; P(deg >= 64) ~ 1e-19

// Scratch (allocation-free __device__ globals).
__device__ int    g_cnt[NN];                        // in-degree histogram
__device__ int    g_cur[NN];                        // bucket fill cursors
__device__ float  g_dinv[NN];                       // rsqrt(deg+1)
__device__ __align__(16) int2   g_bucket[(size_t)NN * CAP];  // {src, norm-bits}
__device__ __align__(16) __half g_t[NN * HH];       // transformed features (gather src)
__device__ __align__(16) __half g_acc[NN * HH];     // layer output (f16)

__device__ __forceinline__ unsigned int pack2(float a, float b) {
    __half2 h = __floats2half2_rn(a, b);
    return *(unsigned int*)&h;
}
__device__ __forceinline__ float2 unpack2(unsigned int u) {
    return __half22float2(*(__half2*)&u);
}

// histogram of dst (edge_index arrives int32; dst row passed directly)
__global__ void hist_kernel(const int* __restrict__ ei_dst) {
    int e = blockIdx.x * blockDim.x + threadIdx.x;
    if (e < EE) atomicAdd(&g_cnt[ei_dst[e]], 1);
}

__global__ void dinv_kernel() {
    int n = blockIdx.x * blockDim.x + threadIdx.x;
    if (n < NN) g_dinv[n] = rsqrtf((float)g_cnt[n] + 1.0f);
}

// Scatter edges into per-dst buckets with precomputed symmetric norm.
__global__ void fill_kernel(const int* __restrict__ ei) {
    int e = blockIdx.x * blockDim.x + threadIdx.x;
    if (e >= EE) return;
    int s = ei[e];
    int d = ei[EE + e];
    float w = g_dinv[s] * g_dinv[d];
    int pos = atomicAdd(&g_cur[d], 1);
    if (pos < CAP)
        g_bucket[(size_t)d * CAP + pos] = make_int2(s, __float_as_int(w));
}

// (optional bias+ReLU of previous f16 layer output) -> h @ W -> g_t (f16).
template <bool FIRST>
__global__ void transform_kernel(const float* __restrict__ in,
                                 const float* __restrict__ W,
                                 const float* __restrict__ bprev) {
    __shared__ float Ws[HH * HH];
    __shared__ float Bs[HH];
    int tid = threadIdx.x;
    if (tid < HH * HH) Ws[tid] = W[tid];
    if (!FIRST && tid < HH) Bs[tid] = bprev[tid];
    __syncthreads();

    int n = blockIdx.x * blockDim.x + tid;
    if (n >= NN) return;

    float h[HH];
    if (FIRST) {
        const float4* p = (const float4*)(in + (size_t)n * HH);
#pragma unroll
        for (int q = 0; q < 4; q++) {
            float4 v = p[q];
            h[q * 4 + 0] = v.x; h[q * 4 + 1] = v.y;
            h[q * 4 + 2] = v.z; h[q * 4 + 3] = v.w;
        }
    } else {
        const uint4* p = (const uint4*)(g_acc + (size_t)n * HH);
#pragma unroll
        for (int q = 0; q < 2; q++) {
            uint4 pk = p[q];
            float2 f0 = unpack2(pk.x), f1 = unpack2(pk.y);
            float2 f2 = unpack2(pk.z), f3 = unpack2(pk.w);
            int b = q * 8;
            h[b + 0] = fmaxf(f0.x + Bs[b + 0], 0.0f);
            h[b + 1] = fmaxf(f0.y + Bs[b + 1], 0.0f);
            h[b + 2] = fmaxf(f1.x + Bs[b + 2], 0.0f);
            h[b + 3] = fmaxf(f1.y + Bs[b + 3], 0.0f);
            h[b + 4] = fmaxf(f2.x + Bs[b + 4], 0.0f);
            h[b + 5] = fmaxf(f2.y + Bs[b + 5], 0.0f);
            h[b + 6] = fmaxf(f3.x + Bs[b + 6], 0.0f);
            h[b + 7] = fmaxf(f3.y + Bs[b + 7], 0.0f);
        }
    }

    float o[HH];
#pragma unroll
    for (int j = 0; j < HH; j++) o[j] = 0.0f;
#pragma unroll
    for (int k = 0; k < HH; k++) {
#pragma unroll
        for (int j = 0; j < HH; j += 4) {
            float4 w = *(const float4*)&Ws[k * HH + j];
            o[j + 0] += h[k] * w.x;
            o[j + 1] += h[k] * w.y;
            o[j + 2] += h[k] * w.z;
            o[j + 3] += h[k] * w.w;
        }
    }

    uint4* tp = (uint4*)(g_t + (size_t)n * HH);
#pragma unroll
    for (int q = 0; q < 2; q++) {
        int b = q * 8;
        uint4 t;
        t.x = pack2(o[b + 0], o[b + 1]);
        t.y = pack2(o[b + 2], o[b + 3]);
        t.z = pack2(o[b + 4], o[b + 5]);
        t.w = pack2(o[b + 6], o[b + 7]);
        tp[q] = t;
    }
}

// Pull aggregation: one warp per node; 4 edge-slots x 8 column-lanes.
// f32 accumulate, zero atomics. Adds self-loop, writes f16 row once.
__global__ void agg_kernel() {
    int gw = (blockIdx.x * blockDim.x + threadIdx.x) >> 5;
    if (gw >= NN) return;
    int lane = threadIdx.x & 31;
    int slot = lane >> 3;      // 0..3
    int col = lane & 7;        // half2 column 0..7

    int deg = g_cnt[gw];
    if (deg > CAP) deg = CAP;
    const int2* bp = g_bucket + (size_t)gw * CAP;

    float2 acc = make_float2(0.0f, 0.0f);
    for (int i = slot; i < deg; i += 4) {
        int2 sn = __ldg(bp + i);
        float w = __int_as_float(sn.y);
        unsigned int pk = __ldg((const unsigned int*)(g_t + (size_t)sn.x * HH) + col);
        float2 f = unpack2(pk);
        acc.x += f.x * w;
        acc.y += f.y * w;
    }
    acc.x += __shfl_down_sync(0xffffffffu, acc.x, 16);
    acc.y += __shfl_down_sync(0xffffffffu, acc.y, 16);
    acc.x += __shfl_down_sync(0xffffffffu, acc.x, 8);
    acc.y += __shfl_down_sync(0xffffffffu, acc.y, 8);

    if (lane < 8) {
        float di = g_dinv[gw];
        float w = di * di;                       // self-loop norm
        unsigned int pk = __ldg((const unsigned int*)(g_t + (size_t)gw * HH) + col);
        float2 f = unpack2(pk);
        acc.x += f.x * w;
        acc.y += f.y * w;
        ((unsigned int*)(g_acc + (size_t)gw * HH))[col] = pack2(acc.x, acc.y);
    }
}

// One block per graph: binary-search sorted batch, block-reduce (f32),
// head + log_softmax.
__global__ void pool_head_kernel(const int* __restrict__ batch,
                                 const float* __restrict__ b3,
                                 const float* __restrict__ Wlin,
                                 const float* __restrict__ blin,
                                 float* __restrict__ out) {
    int g = blockIdx.x;
    int tid = threadIdx.x;

    int lo = 0, hi = NN;
    while (lo < hi) { int m = (lo + hi) >> 1; if (batch[m] < g) lo = m + 1; else hi = m; }
    int beg = lo;
    lo = beg; hi = NN;
    int g1 = g + 1;
    while (lo < hi) { int m = (lo + hi) >> 1; if (batch[m] < g1) lo = m + 1; else hi = m; }
    int end = lo;

    float s[HH];
#pragma unroll
    for (int f = 0; f < HH; f++) s[f] = 0.0f;

    for (int n = beg + tid; n < end; n += blockDim.x) {
        const uint4* p = (const uint4*)(g_acc + (size_t)n * HH);
#pragma unroll
        for (int q = 0; q < 2; q++) {
            uint4 pk = p[q];
            float2 f0 = unpack2(pk.x), f1 = unpack2(pk.y);
            float2 f2 = unpack2(pk.z), f3 = unpack2(pk.w);
            int b = q * 8;
            s[b + 0] += f0.x; s[b + 1] += f0.y;
            s[b + 2] += f1.x; s[b + 3] += f1.y;
            s[b + 4] += f2.x; s[b + 5] += f2.y;
            s[b + 6] += f3.x; s[b + 7] += f3.y;
        }
    }
#pragma unroll
    for (int off = 16; off > 0; off >>= 1) {
#pragma unroll
        for (int f = 0; f < HH; f++)
            s[f] += __shfl_down_sync(0xffffffffu, s[f], off);
    }

    __shared__ float red[8][HH];
    int warp = tid >> 5, lane = tid & 31;
    if (lane == 0) {
#pragma unroll
        for (int f = 0; f < HH; f++) red[warp][f] = s[f];
    }
    __syncthreads();

    if (tid == 0) {
        float tot[HH];
        int nwarps = blockDim.x >> 5;
#pragma unroll
        for (int f = 0; f < HH; f++) {
            float t = 0.0f;
            for (int w = 0; w < nwarps; w++) t += red[w][f];
            tot[f] = t;
        }
        float cnt = (float)(end - beg);
        float inv = 1.0f / fmaxf(cnt, 1.0f);
        float pooled[HH];
#pragma unroll
        for (int f = 0; f < HH; f++) pooled[f] = (tot[f] + cnt * b3[f]) * inv;

        float logit[CC];
#pragma unroll
        for (int c = 0; c < CC; c++) {
            float a = blin[c];
#pragma unroll
            for (int f = 0; f < HH; f++) a += pooled[f] * Wlin[f * CC + c];
            logit[c] = a;
        }
        float m = logit[0];
#pragma unroll
        for (int c = 1; c < CC; c++) m = fmaxf(m, logit[c]);
        float se = 0.0f;
#pragma unroll
        for (int c = 0; c < CC; c++) se += expf(logit[c] - m);
        float lse = m + logf(se);
#pragma unroll
        for (int c = 0; c < CC; c++) out[g * CC + c] = logit[c] - lse;
    }
}

extern "C" void kernel_launch(void* const* d_in, const int* in_sizes, int n_in,
                              void* d_out, int out_size) {
    // Bind inputs by element count (robust to metadata ordering).
    const float *x = 0, *W1 = 0, *b1 = 0, *W2 = 0, *b2 = 0, *W3 = 0, *b3 = 0;
    const float *Wlin = 0, *blin = 0;
    const int *ei = 0, *batch = 0;
    int wseen = 0, bseen = 0;
    for (int i = 0; i < n_in; i++) {
        int s = in_sizes[i];
        const void* p = d_in[i];
        if (s == NN * HH)        x = (const float*)p;
        else if (s == 2 * EE)    ei = (const int*)p;
        else if (s == NN)        batch = (const int*)p;
        else if (s == HH * HH) {
            if (wseen == 0) W1 = (const float*)p;
            else if (wseen == 1) W2 = (const float*)p;
            else W3 = (const float*)p;
            wseen++;
        } else if (s == HH) {
            if (bseen == 0) b1 = (const float*)p;
            else if (bseen == 1) b2 = (const float*)p;
            else b3 = (const float*)p;
            bseen++;
        } else if (s == HH * CC) Wlin = (const float*)p;
        else if (s == CC)        blin = (const float*)p;
    }
    float* out = (float*)d_out;

    static int* cnt_ptr = nullptr;
    static int* cur_ptr = nullptr;
    if (!cnt_ptr) {
        cudaGetSymbolAddress((void**)&cnt_ptr, g_cnt);
        cudaGetSymbolAddress((void**)&cur_ptr, g_cur);
    }

    const int B = 256;
    const int gN = (NN + B - 1) / B;
    const int gE = (EE + B - 1) / B;
    const int gW = (NN * 32 + B - 1) / B;   // warp-per-node aggregation

    cudaMemsetAsync(cnt_ptr, 0, NN * sizeof(int));
    cudaMemsetAsync(cur_ptr, 0, NN * sizeof(int));
    hist_kernel<<<gE, B>>>(ei + EE);
    dinv_kernel<<<gN, B>>>();
    fill_kernel<<<gE, B>>>(ei);

    transform_kernel<true><<<gN, B>>>(x, W1, nullptr);
    agg_kernel<<<gW, B>>>();
    transform_kernel<false><<<gN, B>>>(nullptr, W2, b1);
    agg_kernel<<<gW, B>>>();
    transform_kernel<false><<<gN, B>>>(nullptr, W3, b2);
    agg_kernel<<<gW, B>>>();

    pool_head_kernel<<<GG, B>>>(batch, b3, Wlin, blin, out);
}

// round 15
// speedup vs baseline: 1.4284x; 1.4284x over previous
#include <cuda_runtime.h>
#include <cuda_fp16.h>

#define NN 200000
#define EE 3200000
#define HH 16
#define CC 4
#define GG 256

// Scratch (allocation-free __device__ globals). 16B alignment for vector paths.
__device__ int    g_cnt[NN];                       // in-degree histogram
__device__ float  g_dinv[NN];                      // rsqrt(deg+1)
__device__ __align__(16) int2   g_sd[EE];          // packed (src,dst)
__device__ __align__(16) __half g_t[NN * HH];      // t' = dinv*(h@W), f16 (gather src)
__device__ __align__(16) __half g_acc[NN * HH];    // f16 accumulator (v4.f16x2 RED target)

__device__ __forceinline__ unsigned int pack2(float a, float b) {
    __half2 h = __floats2half2_rn(a, b);
    return *(unsigned int*)&h;
}
__device__ __forceinline__ float2 unpack2(unsigned int u) {
    return __half22float2(*(__half2*)&u);
}

// Read edge_index (int32 from harness) once: pack (src,dst), histogram dst.
__global__ void deg_kernel(const int* __restrict__ ei) {
    int e = blockIdx.x * blockDim.x + threadIdx.x;
    if (e >= EE) return;
    int s = ei[e];
    int d = ei[EE + e];
    g_sd[e] = make_int2(s, d);
    atomicAdd(&g_cnt[d], 1);
}

// Fused: (optional dinv-scale + bias + ReLU of previous accumulator) -> h @ W
// -> t' = o * dinv, written to g_t (f16); g_acc seeded with t' (self-loop term).
// FIRST also computes and stores dinv from the histogram.
template <bool FIRST>
__global__ void transform_kernel(const float* __restrict__ in,
                                 const float* __restrict__ W,
                                 const float* __restrict__ bprev) {
    __shared__ float Ws[HH * HH];
    __shared__ float Bs[HH];
    int tid = threadIdx.x;
    if (tid < HH * HH) Ws[tid] = W[tid];
    if (!FIRST && tid < HH) Bs[tid] = bprev[tid];
    __syncthreads();

    int n = blockIdx.x * blockDim.x + tid;
    if (n >= NN) return;

    float di;
    if (FIRST) {
        di = rsqrtf((float)g_cnt[n] + 1.0f);
        g_dinv[n] = di;
    } else {
        di = g_dinv[n];
    }

    float h[HH];
    if (FIRST) {
        const float4* p = (const float4*)(in + (size_t)n * HH);
#pragma unroll
        for (int q = 0; q < 4; q++) {
            float4 v = p[q];
            h[q * 4 + 0] = v.x; h[q * 4 + 1] = v.y;
            h[q * 4 + 2] = v.z; h[q * 4 + 3] = v.w;
        }
    } else {
        // previous layer: h = relu(dinv * accRaw + b)
        const uint4* p = (const uint4*)(g_acc + (size_t)n * HH);
#pragma unroll
        for (int q = 0; q < 2; q++) {
            uint4 pk = p[q];
            float2 f0 = unpack2(pk.x), f1 = unpack2(pk.y);
            float2 f2 = unpack2(pk.z), f3 = unpack2(pk.w);
            int b = q * 8;
            h[b + 0] = fmaxf(f0.x * di + Bs[b + 0], 0.0f);
            h[b + 1] = fmaxf(f0.y * di + Bs[b + 1], 0.0f);
            h[b + 2] = fmaxf(f1.x * di + Bs[b + 2], 0.0f);
            h[b + 3] = fmaxf(f1.y * di + Bs[b + 3], 0.0f);
            h[b + 4] = fmaxf(f2.x * di + Bs[b + 4], 0.0f);
            h[b + 5] = fmaxf(f2.y * di + Bs[b + 5], 0.0f);
            h[b + 6] = fmaxf(f3.x * di + Bs[b + 6], 0.0f);
            h[b + 7] = fmaxf(f3.y * di + Bs[b + 7], 0.0f);
        }
    }

    float o[HH];
#pragma unroll
    for (int j = 0; j < HH; j++) o[j] = 0.0f;
#pragma unroll
    for (int k = 0; k < HH; k++) {
#pragma unroll
        for (int j = 0; j < HH; j += 4) {
            float4 w = *(const float4*)&Ws[k * HH + j];
            o[j + 0] += h[k] * w.x;
            o[j + 1] += h[k] * w.y;
            o[j + 2] += h[k] * w.z;
            o[j + 3] += h[k] * w.w;
        }
    }

    // t' = o * dinv; g_t and the g_acc seed are the SAME value.
    uint4* tp = (uint4*)(g_t + (size_t)n * HH);
    uint4* ap = (uint4*)(g_acc + (size_t)n * HH);
#pragma unroll
    for (int q = 0; q < 2; q++) {
        int b = q * 8;
        uint4 t;
        t.x = pack2(o[b + 0] * di, o[b + 1] * di);
        t.y = pack2(o[b + 2] * di, o[b + 3] * di);
        t.z = pack2(o[b + 4] * di, o[b + 5] * di);
        t.w = pack2(o[b + 6] * di, o[b + 7] * di);
        tp[q] = t;
        ap[q] = t;
    }
}

// Edge scatter: acc[dst] += t'[src] (UNWEIGHTED). 2 threads/edge, thread c
// handles 8 halves (16B): one 16B f16 gather + ONE red.global.add.noftz.v4.f16x2.
// No norm loads, no multiplies — the dinv[dst] factor is applied by the consumer.
__global__ void scatter_kernel() {
    int gid = blockIdx.x * blockDim.x + threadIdx.x;
    if (gid >= EE * 2) return;
    int e = gid >> 1;
    int c = gid & 1;
    int2 sd = g_sd[e];
    uint4 pk = __ldg((const uint4*)(g_t + (size_t)sd.x * HH) + c);
    __half* a = g_acc + (size_t)sd.y * HH + c * 8;
    asm volatile("red.global.add.noftz.v4.f16x2 [%0], {%1, %2, %3, %4};"
                 :: "l"(a), "r"(pk.x), "r"(pk.y), "r"(pk.z), "r"(pk.w)
                 : "memory");
}

// One block per graph: binary-search sorted batch; per-node h3 = dinv*accRaw
// (b3 added via count trick); block-reduce (f32); head + log_softmax.
__global__ void pool_head_kernel(const int* __restrict__ batch,
                                 const float* __restrict__ b3,
                                 const float* __restrict__ Wlin,
                                 const float* __restrict__ blin,
                                 float* __restrict__ out) {
    int g = blockIdx.x;
    int tid = threadIdx.x;

    int lo = 0, hi = NN;
    while (lo < hi) { int m = (lo + hi) >> 1; if (batch[m] < g) lo = m + 1; else hi = m; }
    int beg = lo;
    lo = beg; hi = NN;
    int g1 = g + 1;
    while (lo < hi) { int m = (lo + hi) >> 1; if (batch[m] < g1) lo = m + 1; else hi = m; }
    int end = lo;

    float s[HH];
#pragma unroll
    for (int f = 0; f < HH; f++) s[f] = 0.0f;

    for (int n = beg + tid; n < end; n += blockDim.x) {
        float di = g_dinv[n];
        const uint4* p = (const uint4*)(g_acc + (size_t)n * HH);
#pragma unroll
        for (int q = 0; q < 2; q++) {
            uint4 pk = p[q];
            float2 f0 = unpack2(pk.x), f1 = unpack2(pk.y);
            float2 f2 = unpack2(pk.z), f3 = unpack2(pk.w);
            int b = q * 8;
            s[b + 0] += f0.x * di; s[b + 1] += f0.y * di;
            s[b + 2] += f1.x * di; s[b + 3] += f1.y * di;
            s[b + 4] += f2.x * di; s[b + 5] += f2.y * di;
            s[b + 6] += f3.x * di; s[b + 7] += f3.y * di;
        }
    }
#pragma unroll
    for (int off = 16; off > 0; off >>= 1) {
#pragma unroll
        for (int f = 0; f < HH; f++)
            s[f] += __shfl_down_sync(0xffffffffu, s[f], off);
    }

    __shared__ float red[8][HH];
    int warp = tid >> 5, lane = tid & 31;
    if (lane == 0) {
#pragma unroll
        for (int f = 0; f < HH; f++) red[warp][f] = s[f];
    }
    __syncthreads();

    if (tid == 0) {
        float tot[HH];
        int nwarps = blockDim.x >> 5;
#pragma unroll
        for (int f = 0; f < HH; f++) {
            float t = 0.0f;
            for (int w = 0; w < nwarps; w++) t += red[w][f];
            tot[f] = t;
        }
        float cnt = (float)(end - beg);
        float inv = 1.0f / fmaxf(cnt, 1.0f);
        float pooled[HH];
#pragma unroll
        for (int f = 0; f < HH; f++) pooled[f] = (tot[f] + cnt * b3[f]) * inv;

        float logit[CC];
#pragma unroll
        for (int c = 0; c < CC; c++) {
            float a = blin[c];
#pragma unroll
            for (int f = 0; f < HH; f++) a += pooled[f] * Wlin[f * CC + c];
            logit[c] = a;
        }
        float m = logit[0];
#pragma unroll
        for (int c = 1; c < CC; c++) m = fmaxf(m, logit[c]);
        float se = 0.0f;
#pragma unroll
        for (int c = 0; c < CC; c++) se += expf(logit[c] - m);
        float lse = m + logf(se);
#pragma unroll
        for (int c = 0; c < CC; c++) out[g * CC + c] = logit[c] - lse;
    }
}

extern "C" void kernel_launch(void* const* d_in, const int* in_sizes, int n_in,
                              void* d_out, int out_size) {
    // Bind inputs by element count (robust to metadata ordering).
    const float *x = 0, *W1 = 0, *b1 = 0, *W2 = 0, *b2 = 0, *W3 = 0, *b3 = 0;
    const float *Wlin = 0, *blin = 0;
    const int *ei = 0, *batch = 0;
    int wseen = 0, bseen = 0;
    for (int i = 0; i < n_in; i++) {
        int s = in_sizes[i];
        const void* p = d_in[i];
        if (s == NN * HH)        x = (const float*)p;
        else if (s == 2 * EE)    ei = (const int*)p;
        else if (s == NN)        batch = (const int*)p;
        else if (s == HH * HH) {
            if (wseen == 0) W1 = (const float*)p;
            else if (wseen == 1) W2 = (const float*)p;
            else W3 = (const float*)p;
            wseen++;
        } else if (s == HH) {
            if (bseen == 0) b1 = (const float*)p;
            else if (bseen == 1) b2 = (const float*)p;
            else b3 = (const float*)p;
            bseen++;
        } else if (s == HH * CC) Wlin = (const float*)p;
        else if (s == CC)        blin = (const float*)p;
    }
    float* out = (float*)d_out;

    static int* cnt_ptr = nullptr;
    if (!cnt_ptr) cudaGetSymbolAddress((void**)&cnt_ptr, g_cnt);

    const int B = 256;
    const int gN = (NN + B - 1) / B;
    const int gE = (EE + B - 1) / B;
    const int gE2 = (EE * 2 + B - 1) / B;

    cudaMemsetAsync(cnt_ptr, 0, NN * sizeof(int));
    deg_kernel<<<gE, B>>>(ei);

    transform_kernel<true><<<gN, B>>>(x, W1, nullptr);    // also computes dinv
    scatter_kernel<<<gE2, B>>>();
    transform_kernel<false><<<gN, B>>>(nullptr, W2, b1);
    scatter_kernel<<<gE2, B>>>();
    transform_kernel<false><<<gN, B>>>(nullptr, W3, b2);
    scatter_kernel<<<gE2, B>>>();

    pool_head_kernel<<<GG, B>>>(batch, b3, Wlin, blin, out);
}

// round 16
// speedup vs baseline: 1.4577x; 1.0205x over previous
#include <cuda_runtime.h>
#include <cuda_fp16.h>

#define NN 200000
#define EE 3200000
#define HH 16
#define CC 4
#define GG 256

// Scratch (allocation-free __device__ globals). 16B alignment for vector paths.
__device__ int    g_cnt[NN];                       // in-degree histogram
__device__ float  g_dinv[NN];                      // rsqrt(deg+1)
__device__ __align__(16) int2   g_sd[EE];          // packed (src,dst)
__device__ __align__(16) __half g_t[NN * HH];      // t' = dinv*(h@W), f16 (gather src)
__device__ __align__(16) __half g_acc[NN * HH];    // f16 accumulator (v4.f16x2 RED target)

__device__ __forceinline__ unsigned int pack2(float a, float b) {
    __half2 h = __floats2half2_rn(a, b);
    return *(unsigned int*)&h;
}
__device__ __forceinline__ float2 unpack2(unsigned int u) {
    return __half22float2(*(__half2*)&u);
}

// Read edge_index (int32 from harness) once: pack (src,dst), histogram dst.
__global__ void deg_kernel(const int* __restrict__ ei) {
    int e = blockIdx.x * blockDim.x + threadIdx.x;
    if (e >= EE) return;
    int s = ei[e];
    int d = ei[EE + e];
    g_sd[e] = make_int2(s, d);
    atomicAdd(&g_cnt[d], 1);
}

// Fused: (optional dinv-scale + bias + ReLU of previous accumulator) -> h @ W
// -> t' = o * dinv, written to g_t (f16); g_acc seeded with t' (self-loop term).
// FIRST also computes and stores dinv. Block size 128 (wave-quantization fix).
template <bool FIRST>
__global__ void __launch_bounds__(128) transform_kernel(const float* __restrict__ in,
                                                        const float* __restrict__ W,
                                                        const float* __restrict__ bprev) {
    __shared__ float Ws[HH * HH];
    __shared__ float Bs[HH];
    int tid = threadIdx.x;
    // 128 threads load 256 W values: 2 each.
    Ws[tid] = W[tid];
    Ws[tid + 128] = W[tid + 128];
    if (!FIRST && tid < HH) Bs[tid] = bprev[tid];
    __syncthreads();

    int n = blockIdx.x * blockDim.x + tid;
    if (n >= NN) return;

    float di;
    if (FIRST) {
        di = rsqrtf((float)g_cnt[n] + 1.0f);
        g_dinv[n] = di;
    } else {
        di = g_dinv[n];
    }

    float h[HH];
    if (FIRST) {
        const float4* p = (const float4*)(in + (size_t)n * HH);
#pragma unroll
        for (int q = 0; q < 4; q++) {
            float4 v = p[q];
            h[q * 4 + 0] = v.x; h[q * 4 + 1] = v.y;
            h[q * 4 + 2] = v.z; h[q * 4 + 3] = v.w;
        }
    } else {
        // previous layer: h = relu(dinv * accRaw + b)
        const uint4* p = (const uint4*)(g_acc + (size_t)n * HH);
#pragma unroll
        for (int q = 0; q < 2; q++) {
            uint4 pk = p[q];
            float2 f0 = unpack2(pk.x), f1 = unpack2(pk.y);
            float2 f2 = unpack2(pk.z), f3 = unpack2(pk.w);
            int b = q * 8;
            h[b + 0] = fmaxf(f0.x * di + Bs[b + 0], 0.0f);
            h[b + 1] = fmaxf(f0.y * di + Bs[b + 1], 0.0f);
            h[b + 2] = fmaxf(f1.x * di + Bs[b + 2], 0.0f);
            h[b + 3] = fmaxf(f1.y * di + Bs[b + 3], 0.0f);
            h[b + 4] = fmaxf(f2.x * di + Bs[b + 4], 0.0f);
            h[b + 5] = fmaxf(f2.y * di + Bs[b + 5], 0.0f);
            h[b + 6] = fmaxf(f3.x * di + Bs[b + 6], 0.0f);
            h[b + 7] = fmaxf(f3.y * di + Bs[b + 7], 0.0f);
        }
    }

    float o[HH];
#pragma unroll
    for (int j = 0; j < HH; j++) o[j] = 0.0f;
#pragma unroll
    for (int k = 0; k < HH; k++) {
#pragma unroll
        for (int j = 0; j < HH; j += 4) {
            float4 w = *(const float4*)&Ws[k * HH + j];
            o[j + 0] += h[k] * w.x;
            o[j + 1] += h[k] * w.y;
            o[j + 2] += h[k] * w.z;
            o[j + 3] += h[k] * w.w;
        }
    }

    // t' = o * dinv; g_t and the g_acc seed are the SAME value.
    uint4* tp = (uint4*)(g_t + (size_t)n * HH);
    uint4* ap = (uint4*)(g_acc + (size_t)n * HH);
#pragma unroll
    for (int q = 0; q < 2; q++) {
        int b = q * 8;
        uint4 t;
        t.x = pack2(o[b + 0] * di, o[b + 1] * di);
        t.y = pack2(o[b + 2] * di, o[b + 3] * di);
        t.z = pack2(o[b + 4] * di, o[b + 5] * di);
        t.w = pack2(o[b + 6] * di, o[b + 7] * di);
        tp[q] = t;
        ap[q] = t;
    }
}

// Edge scatter: acc[dst] += t'[src] (UNWEIGHTED). 2 threads/edge, thread c
// handles 8 halves (16B): one 16B f16 gather + ONE red.global.add.noftz.v4.f16x2.
__global__ void scatter_kernel() {
    int gid = blockIdx.x * blockDim.x + threadIdx.x;
    if (gid >= EE * 2) return;
    int e = gid >> 1;
    int c = gid & 1;
    int2 sd = g_sd[e];
    uint4 pk = __ldg((const uint4*)(g_t + (size_t)sd.x * HH) + c);
    __half* a = g_acc + (size_t)sd.y * HH + c * 8;
    asm volatile("red.global.add.noftz.v4.f16x2 [%0], {%1, %2, %3, %4};"
                 :: "l"(a), "r"(pk.x), "r"(pk.y), "r"(pk.z), "r"(pk.w)
                 : "memory");
}

// One block per graph: binary-search sorted batch; per-node h3 = dinv*accRaw;
// block-reduce (f32); head + log_softmax.
__global__ void pool_head_kernel(const int* __restrict__ batch,
                                 const float* __restrict__ b3,
                                 const float* __restrict__ Wlin,
                                 const float* __restrict__ blin,
                                 float* __restrict__ out) {
    int g = blockIdx.x;
    int tid = threadIdx.x;

    int lo = 0, hi = NN;
    while (lo < hi) { int m = (lo + hi) >> 1; if (batch[m] < g) lo = m + 1; else hi = m; }
    int beg = lo;
    lo = beg; hi = NN;
    int g1 = g + 1;
    while (lo < hi) { int m = (lo + hi) >> 1; if (batch[m] < g1) lo = m + 1; else hi = m; }
    int end = lo;

    float s[HH];
#pragma unroll
    for (int f = 0; f < HH; f++) s[f] = 0.0f;

    for (int n = beg + tid; n < end; n += blockDim.x) {
        float di = g_dinv[n];
        const uint4* p = (const uint4*)(g_acc + (size_t)n * HH);
#pragma unroll
        for (int q = 0; q < 2; q++) {
            uint4 pk = p[q];
            float2 f0 = unpack2(pk.x), f1 = unpack2(pk.y);
            float2 f2 = unpack2(pk.z), f3 = unpack2(pk.w);
            int b = q * 8;
            s[b + 0] += f0.x * di; s[b + 1] += f0.y * di;
            s[b + 2] += f1.x * di; s[b + 3] += f1.y * di;
            s[b + 4] += f2.x * di; s[b + 5] += f2.y * di;
            s[b + 6] += f3.x * di; s[b + 7] += f3.y * di;
        }
    }
#pragma unroll
    for (int off = 16; off > 0; off >>= 1) {
#pragma unroll
        for (int f = 0; f < HH; f++)
            s[f] += __shfl_down_sync(0xffffffffu, s[f], off);
    }

    __shared__ float red[8][HH];
    int warp = tid >> 5, lane = tid & 31;
    if (lane == 0) {
#pragma unroll
        for (int f = 0; f < HH; f++) red[warp][f] = s[f];
    }
    __syncthreads();

    if (tid == 0) {
        float tot[HH];
        int nwarps = blockDim.x >> 5;
#pragma unroll
        for (int f = 0; f < HH; f++) {
            float t = 0.0f;
            for (int w = 0; w < nwarps; w++) t += red[w][f];
            tot[f] = t;
        }
        float cnt = (float)(end - beg);
        float inv = 1.0f / fmaxf(cnt, 1.0f);
        float pooled[HH];
#pragma unroll
        for (int f = 0; f < HH; f++) pooled[f] = (tot[f] + cnt * b3[f]) * inv;

        float logit[CC];
#pragma unroll
        for (int c = 0; c < CC; c++) {
            float a = blin[c];
#pragma unroll
            for (int f = 0; f < HH; f++) a += pooled[f] * Wlin[f * CC + c];
            logit[c] = a;
        }
        float m = logit[0];
#pragma unroll
        for (int c = 1; c < CC; c++) m = fmaxf(m, logit[c]);
        float se = 0.0f;
#pragma unroll
        for (int c = 0; c < CC; c++) se += expf(logit[c] - m);
        float lse = m + logf(se);
#pragma unroll
        for (int c = 0; c < CC; c++) out[g * CC + c] = logit[c] - lse;
    }
}

extern "C" void kernel_launch(void* const* d_in, const int* in_sizes, int n_in,
                              void* d_out, int out_size) {
    // Bind inputs by element count (robust to metadata ordering).
    const float *x = 0, *W1 = 0, *b1 = 0, *W2 = 0, *b2 = 0, *W3 = 0, *b3 = 0;
    const float *Wlin = 0, *blin = 0;
    const int *ei = 0, *batch = 0;
    int wseen = 0, bseen = 0;
    for (int i = 0; i < n_in; i++) {
        int s = in_sizes[i];
        const void* p = d_in[i];
        if (s == NN * HH)        x = (const float*)p;
        else if (s == 2 * EE)    ei = (const int*)p;
        else if (s == NN)        batch = (const int*)p;
        else if (s == HH * HH) {
            if (wseen == 0) W1 = (const float*)p;
            else if (wseen == 1) W2 = (const float*)p;
            else W3 = (const float*)p;
            wseen++;
        } else if (s == HH) {
            if (bseen == 0) b1 = (const float*)p;
            else if (bseen == 1) b2 = (const float*)p;
            else b3 = (const float*)p;
            bseen++;
        } else if (s == HH * CC) Wlin = (const float*)p;
        else if (s == CC)        blin = (const float*)p;
    }
    float* out = (float*)d_out;

    static int* cnt_ptr = nullptr;
    if (!cnt_ptr) cudaGetSymbolAddress((void**)&cnt_ptr, g_cnt);

    const int B = 256;
    const int BT = 128;                       // transform block (load balance)
    const int gT = (NN + BT - 1) / BT;
    const int gE = (EE + 511) / 512;
    const int gE2 = (EE * 2 + B - 1) / B;

    cudaMemsetAsync(cnt_ptr, 0, NN * sizeof(int));
    deg_kernel<<<gE, 512>>>(ei);

    transform_kernel<true><<<gT, BT>>>(x, W1, nullptr);    // also computes dinv
    scatter_kernel<<<gE2, B>>>();
    transform_kernel<false><<<gT, BT>>>(nullptr, W2, b1);
    scatter_kernel<<<gE2, B>>>();
    transform_kernel<false><<<gT, BT>>>(nullptr, W3, b2);
    scatter_kernel<<<gE2, B>>>();

    pool_head_kernel<<<GG, B>>>(batch, b3, Wlin, blin, out);
}

// round 17
// speedup vs baseline: 1.4629x; 1.0036x over previous
#include <cuda_runtime.h>
#include <cuda_fp16.h>

#define NN 200000
#define EE 3200000
#define HH 16
#define CC 4
#define GG 256

// Scratch (allocation-free __device__ globals). 16B alignment for vector paths.
__device__ int    g_cnt[NN];                       // in-degree histogram
__device__ float  g_dinv[NN];                      // rsqrt(deg+1)
__device__ __align__(16) __half g_t[NN * HH];      // t' = dinv*(h@W), f16 (gather src)
__device__ __align__(16) __half g_acc[NN * HH];    // f16 accumulator (v4.f16x2 RED target)

__device__ __forceinline__ unsigned int pack2(float a, float b) {
    __half2 h = __floats2half2_rn(a, b);
    return *(unsigned int*)&h;
}
__device__ __forceinline__ float2 unpack2(unsigned int u) {
    return __half22float2(*(__half2*)&u);
}

// histogram of dst only (12.8 MB read, no edge-copy writes)
__global__ void deg_kernel(const int* __restrict__ ei_dst) {
    int e = blockIdx.x * blockDim.x + threadIdx.x;
    if (e < EE) atomicAdd(&g_cnt[ei_dst[e]], 1);
}

// Fused: (optional dinv-scale + bias + ReLU of previous accumulator) -> h @ W
// -> t' = o * dinv, written to g_t (f16); g_acc seeded with t' (self-loop term).
// FIRST also computes and stores dinv.
template <bool FIRST>
__global__ void __launch_bounds__(128) transform_kernel(const float* __restrict__ in,
                                                        const float* __restrict__ W,
                                                        const float* __restrict__ bprev) {
    __shared__ float Ws[HH * HH];
    __shared__ float Bs[HH];
    int tid = threadIdx.x;
    Ws[tid] = W[tid];
    Ws[tid + 128] = W[tid + 128];
    if (!FIRST && tid < HH) Bs[tid] = bprev[tid];
    __syncthreads();

    int n = blockIdx.x * blockDim.x + tid;
    if (n >= NN) return;

    float di;
    if (FIRST) {
        di = rsqrtf((float)g_cnt[n] + 1.0f);
        g_dinv[n] = di;
    } else {
        di = g_dinv[n];
    }

    float h[HH];
    if (FIRST) {
        const float4* p = (const float4*)(in + (size_t)n * HH);
#pragma unroll
        for (int q = 0; q < 4; q++) {
            float4 v = p[q];
            h[q * 4 + 0] = v.x; h[q * 4 + 1] = v.y;
            h[q * 4 + 2] = v.z; h[q * 4 + 3] = v.w;
        }
    } else {
        // previous layer: h = relu(dinv * accRaw + b)
        const uint4* p = (const uint4*)(g_acc + (size_t)n * HH);
#pragma unroll
        for (int q = 0; q < 2; q++) {
            uint4 pk = p[q];
            float2 f0 = unpack2(pk.x), f1 = unpack2(pk.y);
            float2 f2 = unpack2(pk.z), f3 = unpack2(pk.w);
            int b = q * 8;
            h[b + 0] = fmaxf(f0.x * di + Bs[b + 0], 0.0f);
            h[b + 1] = fmaxf(f0.y * di + Bs[b + 1], 0.0f);
            h[b + 2] = fmaxf(f1.x * di + Bs[b + 2], 0.0f);
            h[b + 3] = fmaxf(f1.y * di + Bs[b + 3], 0.0f);
            h[b + 4] = fmaxf(f2.x * di + Bs[b + 4], 0.0f);
            h[b + 5] = fmaxf(f2.y * di + Bs[b + 5], 0.0f);
            h[b + 6] = fmaxf(f3.x * di + Bs[b + 6], 0.0f);
            h[b + 7] = fmaxf(f3.y * di + Bs[b + 7], 0.0f);
        }
    }

    float o[HH];
#pragma unroll
    for (int j = 0; j < HH; j++) o[j] = 0.0f;
#pragma unroll
    for (int k = 0; k < HH; k++) {
#pragma unroll
        for (int j = 0; j < HH; j += 4) {
            float4 w = *(const float4*)&Ws[k * HH + j];
            o[j + 0] += h[k] * w.x;
            o[j + 1] += h[k] * w.y;
            o[j + 2] += h[k] * w.z;
            o[j + 3] += h[k] * w.w;
        }
    }

    // t' = o * dinv; g_t and the g_acc seed are the SAME value.
    uint4* tp = (uint4*)(g_t + (size_t)n * HH);
    uint4* ap = (uint4*)(g_acc + (size_t)n * HH);
#pragma unroll
    for (int q = 0; q < 2; q++) {
        int b = q * 8;
        uint4 t;
        t.x = pack2(o[b + 0] * di, o[b + 1] * di);
        t.y = pack2(o[b + 2] * di, o[b + 3] * di);
        t.z = pack2(o[b + 4] * di, o[b + 5] * di);
        t.w = pack2(o[b + 6] * di, o[b + 7] * di);
        tp[q] = t;
        ap[q] = t;
    }
}

// Edge scatter: acc[dst] += t'[src] (UNWEIGHTED). 2 threads/edge, thread c
// handles 8 halves (16B): one 16B f16 gather + ONE red.global.add.noftz.v4.f16x2.
// src/dst read directly from edge_index (4B broadcast-coalesced; no g_sd copy).
__global__ void scatter_kernel(const int* __restrict__ ei) {
    int gid = blockIdx.x * blockDim.x + threadIdx.x;
    if (gid >= EE * 2) return;
    int e = gid >> 1;
    int c = gid & 1;
    int s = __ldg(ei + e);
    int d = __ldg(ei + EE + e);
    uint4 pk = __ldg((const uint4*)(g_t + (size_t)s * HH) + c);
    __half* a = g_acc + (size_t)d * HH + c * 8;
    asm volatile("red.global.add.noftz.v4.f16x2 [%0], {%1, %2, %3, %4};"
                 :: "l"(a), "r"(pk.x), "r"(pk.y), "r"(pk.z), "r"(pk.w)
                 : "memory");
}

// One block per graph: binary-search sorted batch; per-node h3 = dinv*accRaw;
// block-reduce (f32); head + log_softmax.
__global__ void pool_head_kernel(const int* __restrict__ batch,
                                 const float* __restrict__ b3,
                                 const float* __restrict__ Wlin,
                                 const float* __restrict__ blin,
                                 float* __restrict__ out) {
    int g = blockIdx.x;
    int tid = threadIdx.x;

    int lo = 0, hi = NN;
    while (lo < hi) { int m = (lo + hi) >> 1; if (batch[m] < g) lo = m + 1; else hi = m; }
    int beg = lo;
    lo = beg; hi = NN;
    int g1 = g + 1;
    while (lo < hi) { int m = (lo + hi) >> 1; if (batch[m] < g1) lo = m + 1; else hi = m; }
    int end = lo;

    float s[HH];
#pragma unroll
    for (int f = 0; f < HH; f++) s[f] = 0.0f;

    for (int n = beg + tid; n < end; n += blockDim.x) {
        float di = g_dinv[n];
        const uint4* p = (const uint4*)(g_acc + (size_t)n * HH);
#pragma unroll
        for (int q = 0; q < 2; q++) {
            uint4 pk = p[q];
            float2 f0 = unpack2(pk.x), f1 = unpack2(pk.y);
            float2 f2 = unpack2(pk.z), f3 = unpack2(pk.w);
            int b = q * 8;
            s[b + 0] += f0.x * di; s[b + 1] += f0.y * di;
            s[b + 2] += f1.x * di; s[b + 3] += f1.y * di;
            s[b + 4] += f2.x * di; s[b + 5] += f2.y * di;
            s[b + 6] += f3.x * di; s[b + 7] += f3.y * di;
        }
    }
#pragma unroll
    for (int off = 16; off > 0; off >>= 1) {
#pragma unroll
        for (int f = 0; f < HH; f++)
            s[f] += __shfl_down_sync(0xffffffffu, s[f], off);
    }

    __shared__ float red[8][HH];
    int warp = tid >> 5, lane = tid & 31;
    if (lane == 0) {
#pragma unroll
        for (int f = 0; f < HH; f++) red[warp][f] = s[f];
    }
    __syncthreads();

    if (tid == 0) {
        float tot[HH];
        int nwarps = blockDim.x >> 5;
#pragma unroll
        for (int f = 0; f < HH; f++) {
            float t = 0.0f;
            for (int w = 0; w < nwarps; w++) t += red[w][f];
            tot[f] = t;
        }
        float cnt = (float)(end - beg);
        float inv = 1.0f / fmaxf(cnt, 1.0f);
        float pooled[HH];
#pragma unroll
        for (int f = 0; f < HH; f++) pooled[f] = (tot[f] + cnt * b3[f]) * inv;

        float logit[CC];
#pragma unroll
        for (int c = 0; c < CC; c++) {
            float a = blin[c];
#pragma unroll
            for (int f = 0; f < HH; f++) a += pooled[f] * Wlin[f * CC + c];
            logit[c] = a;
        }
        float m = logit[0];
#pragma unroll
        for (int c = 1; c < CC; c++) m = fmaxf(m, logit[c]);
        float se = 0.0f;
#pragma unroll
        for (int c = 0; c < CC; c++) se += expf(logit[c] - m);
        float lse = m + logf(se);
#pragma unroll
        for (int c = 0; c < CC; c++) out[g * CC + c] = logit[c] - lse;
    }
}

extern "C" void kernel_launch(void* const* d_in, const int* in_sizes, int n_in,
                              void* d_out, int out_size) {
    // Bind inputs by element count (robust to metadata ordering).
    const float *x = 0, *W1 = 0, *b1 = 0, *W2 = 0, *b2 = 0, *W3 = 0, *b3 = 0;
    const float *Wlin = 0, *blin = 0;
    const int *ei = 0, *batch = 0;
    int wseen = 0, bseen = 0;
    for (int i = 0; i < n_in; i++) {
        int s = in_sizes[i];
        const void* p = d_in[i];
        if (s == NN * HH)        x = (const float*)p;
        else if (s == 2 * EE)    ei = (const int*)p;
        else if (s == NN)        batch = (const int*)p;
        else if (s == HH * HH) {
            if (wseen == 0) W1 = (const float*)p;
            else if (wseen == 1) W2 = (const float*)p;
            else W3 = (const float*)p;
            wseen++;
        } else if (s == HH) {
            if (bseen == 0) b1 = (const float*)p;
            else if (bseen == 1) b2 = (const float*)p;
            else b3 = (const float*)p;
            bseen++;
        } else if (s == HH * CC) Wlin = (const float*)p;
        else if (s == CC)        blin = (const float*)p;
    }
    float* out = (float*)d_out;

    static int* cnt_ptr = nullptr;
    if (!cnt_ptr) cudaGetSymbolAddress((void**)&cnt_ptr, g_cnt);

    const int B = 256;
    const int BT = 128;
    const int gT = (NN + BT - 1) / BT;
    const int gE = (EE + 511) / 512;
    const int gE2 = (EE * 2 + B - 1) / B;

    cudaMemsetAsync(cnt_ptr, 0, NN * sizeof(int));
    deg_kernel<<<gE, 512>>>(ei + EE);        // dst half only

    transform_kernel<true><<<gT, BT>>>(x, W1, nullptr);    // also computes dinv
    scatter_kernel<<<gE2, B>>>(ei);
    transform_kernel<false><<<gT, BT>>>(nullptr, W2, b1);
    scatter_kernel<<<gE2, B>>>(ei);
    transform_kernel<false><<<gT, BT>>>(nullptr, W3, b2);
    scatter_kernel<<<gE2, B>>>(ei);

    pool_head_kernel<<<GG, B>>>(batch, b3, Wlin, blin, out);
}